// round 3
// baseline (speedup 1.0000x reference)
#include <cuda_runtime.h>
#include <cuda_bf16.h>
#include <cstdint>

#define N_NODES 50000
#define N_EDGES 800000
#define NE_TOT  (N_EDGES + N_NODES)   // 850000, self loops appended
#define NG 16

// ---------------- scratch (static device memory; no allocs allowed) ----------------
__device__ __align__(16) float g_big1[N_NODES * 192];   // cols: 0-63 xl1 | 64-127 xr1 | 128-191 hproj1
__device__ __align__(16) float g_big2[N_NODES * 96];    // cols: 0-31 xl2 | 32-63 xr2 | 64-95 hproj2
__device__ __align__(16) float g_acc1[N_NODES * 64];
__device__ __align__(16) float g_den1[N_NODES * 2];
__device__ __align__(16) float g_out1[N_NODES * 64];
__device__ __align__(16) float g_h[N_NODES * 64];
__device__ __align__(16) float g_acc2[N_NODES * 32];
__device__ __align__(16) float g_den2[N_NODES];
__device__ __align__(16) float g_out2[N_NODES * 32];
__device__ __align__(16) float g_Wcat1[128 * 192];
__device__ __align__(16) float g_bcat1[192];
__device__ __align__(16) float g_Wcat2[64 * 96];
__device__ __align__(16) float g_bcat2[96];
__device__ __align__(16) float g_easum[16];
__device__ __align__(16) float g_eself1[64];
__device__ __align__(16) float g_eself2[32];
__device__ __align__(16) float g_bnsum[128];     // [0:64) sum, [64:128) sumsq
__device__ __align__(16) float g_bnsc1[128];     // [0:64) scale, [64:128) shift
__device__ __align__(16) float g_bnsum2[64];
__device__ __align__(16) float g_bnsc2[64];
__device__ __align__(16) float g_psum[NG * 32];
__device__ __align__(16) float g_pmax[NG * 32];
__device__ int g_cnt[NG];

// ---------------- helpers ----------------
__device__ __forceinline__ float lrelu(float v) { return v > 0.f ? v : 0.2f * v; }

__device__ __forceinline__ void red4(float* p, float4 v) {
    asm volatile("red.global.add.v4.f32 [%0], {%1,%2,%3,%4};"
                 :: "l"(p), "f"(v.x), "f"(v.y), "f"(v.z), "f"(v.w) : "memory");
}

__device__ __forceinline__ void atomicMaxF(float* addr, float v) {
    if (v >= 0.f) atomicMax((int*)addr, __float_as_int(v));
    else          atomicMin((unsigned int*)addr, __float_as_uint(v));
}
__device__ __forceinline__ void atomicMaxFs(float* addr, float v) {  // shared-mem version
    if (v >= 0.f) atomicMax((int*)addr, __float_as_int(v));
    else          atomicMin((unsigned int*)addr, __float_as_uint(v));
}

// ---------------- clear ----------------
__global__ void clear_kernel() {
    int i  = blockIdx.x * blockDim.x + threadIdx.x;
    int st = gridDim.x * blockDim.x;
    for (int j = i; j < N_NODES * 64; j += st) g_acc1[j] = 0.f;
    for (int j = i; j < N_NODES * 32; j += st) g_acc2[j] = 0.f;
    for (int j = i; j < N_NODES * 2;  j += st) g_den1[j] = 0.f;
    for (int j = i; j < N_NODES;      j += st) g_den2[j] = 0.f;
    if (i < 16)  g_easum[i] = 0.f;
    if (i < 128) g_bnsum[i] = 0.f;
    if (i < 64)  g_bnsum2[i] = 0.f;
    if (i < NG * 32) { g_psum[i] = 0.f; g_pmax[i] = __int_as_float(0xff800000); }
    if (i < NG)  g_cnt[i] = 0;
}

// ---------------- weight packing ----------------
__global__ void pack1_kernel(const float* __restrict__ Wl, const float* __restrict__ bl,
                             const float* __restrict__ Wr, const float* __restrict__ br,
                             const float* __restrict__ Ws, const float* __restrict__ bs) {
    int i = blockIdx.x * blockDim.x + threadIdx.x;
    if (i < 128 * 64) {
        int k = i >> 6, j = i & 63;
        g_Wcat1[k * 192 + j]       = Wl[i];
        g_Wcat1[k * 192 + 64 + j]  = Wr[i];
        g_Wcat1[k * 192 + 128 + j] = Ws[i];
    }
    if (i < 64) { g_bcat1[i] = bl[i]; g_bcat1[64 + i] = br[i]; g_bcat1[128 + i] = bs[i]; }
}

__global__ void pack2_kernel(const float* __restrict__ Wl, const float* __restrict__ bl,
                             const float* __restrict__ Wr, const float* __restrict__ br,
                             const float* __restrict__ Ws, const float* __restrict__ bs) {
    int i = blockIdx.x * blockDim.x + threadIdx.x;
    if (i < 64 * 32) {
        int k = i >> 5, j = i & 31;
        g_Wcat2[k * 96 + j]      = Wl[i];
        g_Wcat2[k * 96 + 32 + j] = Wr[i];
        g_Wcat2[k * 96 + 64 + j] = Ws[i];
    }
    if (i < 32) { g_bcat2[i] = bl[i]; g_bcat2[32 + i] = br[i]; g_bcat2[64 + i] = bs[i]; }
}

// ---------------- edge_attr mean ----------------
__global__ void easum_kernel(const float* __restrict__ ea) {
    int tid = threadIdx.x;
    int c = tid & 15;
    float s = 0.f;
    for (int r = blockIdx.x * 16 + (tid >> 4); r < N_EDGES; r += gridDim.x * 16)
        s += ea[r * 16 + c];
    __shared__ float sm[256];
    sm[tid] = s;
    __syncthreads();
    if (tid < 16) {
        float t = 0.f;
        #pragma unroll
        for (int g = 0; g < 16; g++) t += sm[g * 16 + tid];
        atomicAdd(&g_easum[tid], t);
    }
}

__global__ void eself_kernel(const float* __restrict__ We1, const float* __restrict__ We2) {
    __shared__ float m[16];
    int t = threadIdx.x;
    if (t < 16) m[t] = g_easum[t] * (1.0f / N_EDGES);
    __syncthreads();
    if (t < 64) {
        float s = 0.f;
        #pragma unroll
        for (int k = 0; k < 16; k++) s += m[k] * We1[k * 64 + t];
        g_eself1[t] = s;
    }
    if (t < 32) {
        float s = 0.f;
        #pragma unroll
        for (int k = 0; k < 16; k++) s += m[k] * We2[k * 32 + t];
        g_eself2[t] = s;
    }
}

// ---------------- tiled GEMM: C[M,NT] = A[M,K] @ W[K,NT] + bias ----------------
template <int K, int NT>
__device__ __forceinline__ void gemm_body(const float* __restrict__ A,
                                          const float* __restrict__ W,
                                          const float* __restrict__ bias,
                                          float* __restrict__ C, int M) {
    __shared__ __align__(16) float As[16][65];
    __shared__ float Bs[16][100];
    const int bm = blockIdx.x * 64;
    const int bn = blockIdx.y * 96;
    const int tid = threadIdx.x;
    const int tx = tid & 15, ty = tid >> 4;
    float acc[4][6];
    #pragma unroll
    for (int i = 0; i < 4; i++)
        #pragma unroll
        for (int j = 0; j < 6; j++) acc[i][j] = 0.f;
    const int ar = tid >> 2, ac = (tid & 3) << 2;
    for (int k0 = 0; k0 < K; k0 += 16) {
        float4 av = make_float4(0.f, 0.f, 0.f, 0.f);
        int row = bm + ar;
        if (row < M) av = *(const float4*)&A[row * K + k0 + ac];
        As[ac][ar] = av.x; As[ac + 1][ar] = av.y; As[ac + 2][ar] = av.z; As[ac + 3][ar] = av.w;
        #pragma unroll
        for (int i = 0; i < 6; i++) {
            int idx = tid + (i << 8);
            int r = idx / 96, cc = idx - r * 96;
            Bs[r][cc] = W[(k0 + r) * NT + bn + cc];
        }
        __syncthreads();
        #pragma unroll
        for (int kk = 0; kk < 16; kk++) {
            float a[4], b[6];
            #pragma unroll
            for (int i = 0; i < 4; i++) a[i] = As[kk][(ty << 2) + i];
            #pragma unroll
            for (int j = 0; j < 6; j++) b[j] = Bs[kk][tx * 6 + j];
            #pragma unroll
            for (int i = 0; i < 4; i++)
                #pragma unroll
                for (int j = 0; j < 6; j++) acc[i][j] += a[i] * b[j];
        }
        __syncthreads();
    }
    #pragma unroll
    for (int i = 0; i < 4; i++) {
        int r = bm + (ty << 2) + i;
        if (r < M) {
            #pragma unroll
            for (int j = 0; j < 6; j++) {
                int cc = bn + tx * 6 + j;
                C[r * NT + cc] = acc[i][j] + bias[cc];
            }
        }
    }
}

__global__ void gemm1_kernel(const float* __restrict__ A) {
    gemm_body<128, 192>(A, g_Wcat1, g_bcat1, g_big1, N_NODES);
}
__global__ void gemm2_kernel() {
    gemm_body<64, 96>(g_h, g_Wcat2, g_bcat2, g_big2, N_NODES);
}

// ---------------- edge kernel layer 1 (H=2, C=32; 2 edges per warp) ----------------
__global__ void edge1_kernel(const int* __restrict__ ei, const float* __restrict__ ea,
                             const float* __restrict__ We, const float* __restrict__ att) {
    __shared__ __align__(16) float sWe[16 * 64];
    __shared__ __align__(16) float sAtt[64];
    __shared__ __align__(16) float sEself[64];
    for (int i = threadIdx.x; i < 16 * 64; i += blockDim.x) sWe[i] = We[i];
    if (threadIdx.x < 64) { sAtt[threadIdx.x] = att[threadIdx.x]; sEself[threadIdx.x] = g_eself1[threadIdx.x]; }
    __syncthreads();
    const int lane = threadIdx.x & 31;
    const int sub  = lane & 15;          // 0..15 -> 4 channels each
    const int head = sub >> 3;           // 0 or 1
    const int half = lane >> 4;          // edge within pair
    const int warp = threadIdx.x >> 5;
    const int nwarps = (gridDim.x * blockDim.x) >> 5;
    const int gw = blockIdx.x * (blockDim.x >> 5) + warp;
    const int npairs = (NE_TOT + 1) >> 1;
    const float4 a4  = *(const float4*)&sAtt[4 * sub];
    const float4 es4 = *(const float4*)&sEself[4 * sub];
    for (int pair = gw; pair < npairs; pair += nwarps) {
        int e = pair * 2 + half;
        bool valid = e < NE_TOT;
        int s = 0, d = 0;
        bool isloop = false;
        if (valid) {
            if (e < N_EDGES) { s = ei[e]; d = ei[N_EDGES + e]; }
            else             { s = d = e - N_EDGES; isloop = true; }
        }
        int eidx = (valid && !isloop) ? e : 0;
        float eav = ea[eidx * 16 + sub];
        float4 e4 = make_float4(0.f, 0.f, 0.f, 0.f);
        #pragma unroll
        for (int k = 0; k < 16; k++) {
            float a = __shfl_sync(0xffffffffu, eav, k, 16);
            float4 w4 = *(const float4*)&sWe[k * 64 + 4 * sub];
            e4.x += a * w4.x; e4.y += a * w4.y; e4.z += a * w4.z; e4.w += a * w4.w;
        }
        if (isloop) e4 = es4;
        const float* xlp = g_big1 + s * 192;
        const float* xrp = g_big1 + d * 192 + 64;
        float4 xl4 = *(const float4*)&xlp[4 * sub];
        float4 xr4 = *(const float4*)&xrp[4 * sub];
        float4 mm;
        mm.x = lrelu(xl4.x + xr4.x + e4.x);
        mm.y = lrelu(xl4.y + xr4.y + e4.y);
        mm.z = lrelu(xl4.z + xr4.z + e4.z);
        mm.w = lrelu(xl4.w + xr4.w + e4.w);
        float p = mm.x * a4.x + mm.y * a4.y + mm.z * a4.z + mm.w * a4.w;
        p += __shfl_xor_sync(0xffffffffu, p, 4);
        p += __shfl_xor_sync(0xffffffffu, p, 2);
        p += __shfl_xor_sync(0xffffffffu, p, 1);
        float w = __expf(p);
        if (valid) {
            if ((sub & 7) == 0) atomicAdd(&g_den1[d * 2 + head], w);
            float4 r = make_float4(w * xl4.x, w * xl4.y, w * xl4.z, w * xl4.w);
            red4(&g_acc1[d * 64 + 4 * sub], r);
        }
    }
}

// ---------------- edge kernel layer 2 (H=1, C=32; 4 edges per warp) ----------------
__global__ void edge2_kernel(const int* __restrict__ ei, const float* __restrict__ ea,
                             const float* __restrict__ We, const float* __restrict__ att) {
    __shared__ __align__(16) float sWe[16 * 32];
    __shared__ __align__(16) float sAtt[32];
    __shared__ __align__(16) float sEself[32];
    for (int i = threadIdx.x; i < 512; i += blockDim.x) sWe[i] = We[i];
    if (threadIdx.x < 32) { sAtt[threadIdx.x] = att[threadIdx.x]; sEself[threadIdx.x] = g_eself2[threadIdx.x]; }
    __syncthreads();
    const int lane = threadIdx.x & 31;
    const int grp = lane >> 3, sub = lane & 7;
    const int warp = threadIdx.x >> 5;
    const int nwarps = (gridDim.x * blockDim.x) >> 5;
    const int gw = blockIdx.x * (blockDim.x >> 5) + warp;
    const int nquads = (NE_TOT + 3) >> 2;
    const float4 a4  = *(const float4*)&sAtt[4 * sub];
    const float4 es4 = *(const float4*)&sEself[4 * sub];
    for (int q = gw; q < nquads; q += nwarps) {
        int e = q * 4 + grp;
        bool valid = e < NE_TOT;
        int s = 0, d = 0;
        bool isloop = false;
        if (valid) {
            if (e < N_EDGES) { s = ei[e]; d = ei[N_EDGES + e]; }
            else             { s = d = e - N_EDGES; isloop = true; }
        }
        int eidx = (valid && !isloop) ? e : 0;
        float ev0 = ea[eidx * 16 + sub];
        float ev1 = ea[eidx * 16 + 8 + sub];
        float4 e4 = make_float4(0.f, 0.f, 0.f, 0.f);
        #pragma unroll
        for (int k = 0; k < 8; k++) {
            float a = __shfl_sync(0xffffffffu, ev0, k, 8);
            float4 w4 = *(const float4*)&sWe[k * 32 + 4 * sub];
            e4.x += a * w4.x; e4.y += a * w4.y; e4.z += a * w4.z; e4.w += a * w4.w;
        }
        #pragma unroll
        for (int k = 0; k < 8; k++) {
            float a = __shfl_sync(0xffffffffu, ev1, k, 8);
            float4 w4 = *(const float4*)&sWe[(8 + k) * 32 + 4 * sub];
            e4.x += a * w4.x; e4.y += a * w4.y; e4.z += a * w4.z; e4.w += a * w4.w;
        }
        if (isloop) e4 = es4;
        const float* xlp = g_big2 + s * 96;
        const float* xrp = g_big2 + d * 96 + 32;
        float4 xl4 = *(const float4*)&xlp[4 * sub];
        float4 xr4 = *(const float4*)&xrp[4 * sub];
        float4 mm;
        mm.x = lrelu(xl4.x + xr4.x + e4.x);
        mm.y = lrelu(xl4.y + xr4.y + e4.y);
        mm.z = lrelu(xl4.z + xr4.z + e4.z);
        mm.w = lrelu(xl4.w + xr4.w + e4.w);
        float p = mm.x * a4.x + mm.y * a4.y + mm.z * a4.z + mm.w * a4.w;
        p += __shfl_xor_sync(0xffffffffu, p, 4);
        p += __shfl_xor_sync(0xffffffffu, p, 2);
        p += __shfl_xor_sync(0xffffffffu, p, 1);
        float w = __expf(p);
        if (valid) {
            if (sub == 0) atomicAdd(&g_den2[d], w);
            float4 r = make_float4(w * xl4.x, w * xl4.y, w * xl4.z, w * xl4.w);
            red4(&g_acc2[d * 32 + 4 * sub], r);
        }
    }
}

// ---------------- finalize conv1: out1 = acc/den + bias, accumulate BN stats ----------------
__global__ void final1_kernel(const float* __restrict__ bias) {
    int tid = threadIdx.x;
    int c = tid & 63;
    int h = c >> 5;
    float s = 0.f, q = 0.f;
    for (int n = blockIdx.x * 4 + (tid >> 6); n < N_NODES; n += gridDim.x * 4) {
        float v = g_acc1[n * 64 + c] / (g_den1[n * 2 + h] + 1e-16f) + bias[c];
        g_out1[n * 64 + c] = v;
        s += v; q += v * v;
    }
    __shared__ float ss[256], sq[256];
    ss[tid] = s; sq[tid] = q;
    __syncthreads();
    if (tid < 64) {
        s = ss[tid] + ss[tid + 64] + ss[tid + 128] + ss[tid + 192];
        q = sq[tid] + sq[tid + 64] + sq[tid + 128] + sq[tid + 192];
        atomicAdd(&g_bnsum[tid], s);
        atomicAdd(&g_bnsum[64 + tid], q);
    }
}

__global__ void bnfin1_kernel(const float* __restrict__ g, const float* __restrict__ b) {
    int c = threadIdx.x;
    if (c < 64) {
        float mean = g_bnsum[c] * (1.0f / N_NODES);
        float var  = g_bnsum[64 + c] * (1.0f / N_NODES) - mean * mean;
        float sc   = g[c] * rsqrtf(var + 1e-5f);
        g_bnsc1[c] = sc;
        g_bnsc1[64 + c] = b[c] - mean * sc;
    }
}

__global__ void elu1_kernel() {
    int i = blockIdx.x * blockDim.x + threadIdx.x;
    int st = gridDim.x * blockDim.x;
    for (; i < N_NODES * 64; i += st) {
        int n = i >> 6, c = i & 63;
        float v = g_out1[i] * g_bnsc1[c] + g_bnsc1[64 + c] + g_big1[n * 192 + 128 + c];
        g_h[i] = v > 0.f ? v : expm1f(v);
    }
}

// ---------------- finalize conv2 ----------------
__global__ void final2_kernel(const float* __restrict__ bias) {
    int tid = threadIdx.x;
    int c = tid & 31;
    float s = 0.f, q = 0.f;
    for (int n = blockIdx.x * 8 + (tid >> 5); n < N_NODES; n += gridDim.x * 8) {
        float v = g_acc2[n * 32 + c] / (g_den2[n] + 1e-16f) + bias[c];
        g_out2[n * 32 + c] = v;
        s += v; q += v * v;
    }
    __shared__ float ss[256], sq[256];
    ss[tid] = s; sq[tid] = q;
    __syncthreads();
    if (tid < 32) {
        s = 0.f; q = 0.f;
        #pragma unroll
        for (int gg = 0; gg < 8; gg++) { s += ss[tid + gg * 32]; q += sq[tid + gg * 32]; }
        atomicAdd(&g_bnsum2[tid], s);
        atomicAdd(&g_bnsum2[32 + tid], q);
    }
}

__global__ void bnfin2_kernel(const float* __restrict__ g, const float* __restrict__ b) {
    int c = threadIdx.x;
    if (c < 32) {
        float mean = g_bnsum2[c] * (1.0f / N_NODES);
        float var  = g_bnsum2[32 + c] * (1.0f / N_NODES) - mean * mean;
        float sc   = g[c] * rsqrtf(var + 1e-5f);
        g_bnsc2[c] = sc;
        g_bnsc2[32 + c] = b[c] - mean * sc;
    }
}

// ---------------- elu2 + graph pooling (smem pre-reduction; batch is sorted) ----------------
__global__ void elu2pool_kernel(const int* __restrict__ batch) {
    __shared__ float ssum[NG * 32];
    __shared__ float smax[NG * 32];
    __shared__ int scnt[NG];
    int tid = threadIdx.x;
    for (int i = tid; i < NG * 32; i += blockDim.x) { ssum[i] = 0.f; smax[i] = __int_as_float(0xff800000); }
    if (tid < NG) scnt[tid] = 0;
    __syncthreads();
    int c = tid & 31;
    for (int n = blockIdx.x * 8 + (tid >> 5); n < N_NODES; n += gridDim.x * 8) {
        float v = g_out2[n * 32 + c] * g_bnsc2[c] + g_bnsc2[32 + c] + g_big2[n * 96 + 64 + c];
        v = v > 0.f ? v : expm1f(v);
        int g = batch[n];
        atomicAdd(&ssum[g * 32 + c], v);
        atomicMaxFs(&smax[g * 32 + c], v);
        if (c == 0) atomicAdd(&scnt[g], 1);
    }
    __syncthreads();
    for (int i = tid; i < NG * 32; i += blockDim.x) {
        atomicAdd(&g_psum[i], ssum[i]);
        atomicMaxF(&g_pmax[i], smax[i]);
    }
    if (tid < NG) atomicAdd(&g_cnt[tid], scnt[tid]);
}

__global__ void finalout_kernel(float* __restrict__ out) {
    int tid = threadIdx.x;
    if (tid < NG * 64) {
        int g = tid >> 6, j = tid & 63;
        int cnt = g_cnt[g];
        float r;
        if (j < 32) r = g_psum[g * 32 + j] / fmaxf((float)cnt, 1.0f);
        else        r = (cnt > 0) ? g_pmax[g * 32 + (j - 32)] : 0.0f;
        out[tid] = r;
    }
}

// ---------------- launch ----------------
extern "C" void kernel_launch(void* const* d_in, const int* in_sizes, int n_in,
                              void* d_out, int out_size) {
    const float* x     = (const float*)d_in[0];
    const int*   ei    = (const int*)d_in[1];
    const float* ea    = (const float*)d_in[2];
    const int*   batch = (const int*)d_in[3];
    const float* s1W = (const float*)d_in[4];
    const float* s1b = (const float*)d_in[5];
    const float* c1Wl = (const float*)d_in[6];
    const float* c1bl = (const float*)d_in[7];
    const float* c1Wr = (const float*)d_in[8];
    const float* c1br = (const float*)d_in[9];
    const float* c1We = (const float*)d_in[10];
    const float* c1att = (const float*)d_in[11];
    const float* c1bias = (const float*)d_in[12];
    const float* bn1g = (const float*)d_in[13];
    const float* bn1b = (const float*)d_in[14];
    const float* s2W = (const float*)d_in[15];
    const float* s2b = (const float*)d_in[16];
    const float* c2Wl = (const float*)d_in[17];
    const float* c2bl = (const float*)d_in[18];
    const float* c2Wr = (const float*)d_in[19];
    const float* c2br = (const float*)d_in[20];
    const float* c2We = (const float*)d_in[21];
    const float* c2att = (const float*)d_in[22];
    const float* c2bias = (const float*)d_in[23];
    const float* bn2g = (const float*)d_in[24];
    const float* bn2b = (const float*)d_in[25];
    float* out = (float*)d_out;

    clear_kernel<<<2048, 256>>>();
    pack1_kernel<<<32, 256>>>(c1Wl, c1bl, c1Wr, c1br, s1W, s1b);
    pack2_kernel<<<8, 256>>>(c2Wl, c2bl, c2Wr, c2br, s2W, s2b);
    easum_kernel<<<512, 256>>>(ea);
    eself_kernel<<<1, 64>>>(c1We, c2We);

    gemm1_kernel<<<dim3((N_NODES + 63) / 64, 2), 256>>>(x);
    edge1_kernel<<<2048, 256>>>(ei, ea, c1We, c1att);
    final1_kernel<<<512, 256>>>(c1bias);
    bnfin1_kernel<<<1, 64>>>(bn1g, bn1b);
    elu1_kernel<<<2048, 256>>>();

    gemm2_kernel<<<dim3((N_NODES + 63) / 64, 1), 256>>>();
    edge2_kernel<<<1536, 256>>>(ei, ea, c2We, c2att);
    final2_kernel<<<512, 256>>>(c2bias);
    bnfin2_kernel<<<1, 32>>>(bn2g, bn2b);
    elu2pool_kernel<<<256, 256>>>(batch);
    finalout_kernel<<<1, 1024>>>(out);
}